// round 6
// baseline (speedup 1.0000x reference)
#include <cuda_runtime.h>
#include <math.h>
#include <stdint.h>

#define EPSV 1e-5f
typedef unsigned long long ull;

// ---------------- f32x2 helpers ---------------------------------------------
static __device__ __forceinline__ ull pk2(float lo, float hi) {
    ull r; asm("mov.b64 %0,{%1,%2};" : "=l"(r) : "f"(lo), "f"(hi)); return r;
}
static __device__ __forceinline__ void upk2(ull v, float& lo, float& hi) {
    asm("mov.b64 {%0,%1},%2;" : "=f"(lo), "=f"(hi) : "l"(v));
}
static __device__ __forceinline__ ull f2fma(ull a, ull b, ull c) {
    ull r; asm("fma.rn.f32x2 %0,%1,%2,%3;" : "=l"(r) : "l"(a), "l"(b), "l"(c)); return r;
}
static __device__ __forceinline__ ull f2add(ull a, ull b) {
    ull r; asm("add.rn.f32x2 %0,%1,%2;" : "=l"(r) : "l"(a), "l"(b)); return r;
}

// ---------------- scratch ----------------------------------------------------
__device__ float g_xt[1 * 16 * 16 * 1024];
__device__ float g_h1[16 * 14 * 14 * 1024];
__device__ float g_h2[32 * 12 * 12 * 1024];
__device__ float g_h3[64 * 10 * 10 * 1024];          // pre-BN (BN3 fused in FC)
__device__ float g_stats[224];
__device__ float g_part[25 * 10 * 1024];
// transposed weights: T[loc][o][k], k = c*9+ij
__device__ float g_w1t[196 * 16 * 9];
__device__ float g_w2t[144 * 32 * 144];
__device__ float g_w3t[100 * 64 * 288];

// ---------------- fused prep: transpose x + zero stats + weight reorder -----
__global__ void prep_kernel(const float* __restrict__ x,
                            const float* __restrict__ W1,
                            const float* __restrict__ W2,
                            const float* __restrict__ W3) {
    int bid = blockIdx.x;
    if (bid < 256) {
        __shared__ float tile[32][33];
        int bx = bid % 8, by = bid / 8;
        int tx = threadIdx.x % 32, ty = threadIdx.x / 32;
        for (int r = 0; r < 4; r++) {
            int p = bx * 32 + tx;
            int b = by * 32 + ty + r * 8;
            tile[ty + r * 8][tx] = x[b * 256 + p];
        }
        __syncthreads();
        for (int r = 0; r < 4; r++) {
            int p2 = bx * 32 + ty + r * 8;
            int b2 = by * 32 + tx;
            g_xt[p2 * 1024 + b2] = tile[tx][ty + r * 8];
        }
        return;
    }
    if (bid == 256) {
        if (threadIdx.x < 224) g_stats[threadIdx.x] = 0.f;
        return;
    }
    long idx = (long)(bid - 257) * 256 + threadIdx.x;
    if (idx < 28224) {
        int k = idx % 9, o = (idx / 9) % 16, loc = idx / (9 * 16);
        g_w1t[idx] = W1[(((o * 1) * 14 + loc / 14) * 14 + loc % 14) * 9 + k];
        return;
    }
    idx -= 28224;
    if (idx < 663552) {
        int k = idx % 144, o = (idx / 144) % 32, loc = idx / (144 * 32);
        int c = k / 9, ij = k % 9;
        g_w2t[idx] = W2[((((o * 16 + c) * 12 + loc / 12) * 12 + loc % 12)) * 9 + ij];
        return;
    }
    idx -= 663552;
    if (idx < 1843200) {
        int k = idx % 288, o = (idx / 288) % 64, loc = idx / (288 * 64);
        int c = k / 9, ij = k % 9;
        g_w3t[idx] = W3[((((o * 32 + c) * 10 + loc / 10) * 10 + loc % 10)) * 9 + ij];
    }
}

// ---------------- small LC (layer 1, C=1): direct-LDG version ---------------
template <int C, int HIN, int OH, int O_TOT, int MINB>
__global__ void __launch_bounds__(64, MINB)
lc_small_kernel(const float* __restrict__ in, const float* __restrict__ WT,
                const float* __restrict__ bias, float* __restrict__ out,
                float* __restrict__ stats_out) {
    constexpr int KK  = C * 9;
    constexpr int C10 = C * 10;

    const int loc    = blockIdx.x;
    const int o_base = blockIdx.z * 16;
    const int lane   = threadIdx.x;
    const int b0     = blockIdx.y * 256 + lane * 2;
    const int tid    = threadIdx.y * 32 + lane;
    const int ogrp   = threadIdx.y;

    extern __shared__ __align__(16) unsigned char smraw[];
    ull* Ws2 = (ull*)smraw;

    const float* wsrc = WT + ((size_t)loc * O_TOT + o_base) * KK;
    for (int lin = tid; lin < 16 * KK; lin += 64) {
        int o = lin / KK, k = lin % KK;
        float w = wsrc[lin];
        Ws2[o * C10 + (k / 9) * 10 + (k % 9)] = pk2(w, w);
    }
    __syncthreads();

    ull acc[8][4];
#pragma unroll
    for (int o = 0; o < 8; o++)
#pragma unroll
        for (int m = 0; m < 4; m++) acc[o][m] = 0ull;

    const ull* wp = Ws2 + ogrp * 8 * C10;
    const float* cp = in + ((size_t)(loc / OH) * HIN + (loc % OH)) * 1024 + b0;

    for (int c = 0; c < C; c++) {
#pragma unroll
        for (int p = 0; p < 4; p++) {
            const int ij0 = 2 * p, ij1 = 2 * p + 1;
            const int off0 = ((ij0 / 3) * HIN + (ij0 % 3)) * 1024;
            const int off1 = ((ij1 / 3) * HIN + (ij1 % 3)) * 1024;
            ull v0[4], v1[4];
#pragma unroll
            for (int m = 0; m < 4; m++) v0[m] = *(const ull*)(cp + off0 + 64 * m);
#pragma unroll
            for (int m = 0; m < 4; m++) v1[m] = *(const ull*)(cp + off1 + 64 * m);
#pragma unroll
            for (int o = 0; o < 8; o++) {
                ulonglong2 w = *(const ulonglong2*)&wp[o * C10 + c * 10 + 2 * p];
#pragma unroll
                for (int m = 0; m < 4; m++) acc[o][m] = f2fma(v0[m], w.x, acc[o][m]);
#pragma unroll
                for (int m = 0; m < 4; m++) acc[o][m] = f2fma(v1[m], w.y, acc[o][m]);
            }
        }
        {
            const int off = (2 * HIN + 2) * 1024;
            ull v[4];
#pragma unroll
            for (int m = 0; m < 4; m++) v[m] = *(const ull*)(cp + off + 64 * m);
#pragma unroll
            for (int o = 0; o < 8; o++) {
                ull w2 = wp[o * C10 + c * 10 + 8];
#pragma unroll
                for (int m = 0; m < 4; m++) acc[o][m] = f2fma(v[m], w2, acc[o][m]);
            }
        }
        cp += HIN * HIN * 1024;
    }

#pragma unroll
    for (int o = 0; o < 8; o++) {
        int og = o_base + ogrp * 8 + o;
        float bb = __ldg(&bias[og * OH * OH + loc]);
        ull b2 = pk2(bb, bb);
        float* op = out + ((size_t)og * OH * OH + loc) * 1024 + b0;
        ull s2 = 0ull, q2 = 0ull;
#pragma unroll
        for (int m = 0; m < 4; m++) {
            ull r = f2add(acc[o][m], b2);
            *(ull*)(op + 64 * m) = r;
            s2 = f2add(s2, r);
            q2 = f2fma(r, r, q2);
        }
        float sl, sh, ql, qh;
        upk2(s2, sl, sh); upk2(q2, ql, qh);
        float s = sl + sh, q = ql + qh;
#pragma unroll
        for (int off = 16; off > 0; off >>= 1) {
            s += __shfl_down_sync(0xffffffffu, s, off);
            q += __shfl_down_sync(0xffffffffu, q, off);
        }
        if (lane == 0) {
            atomicAdd(&stats_out[og * 2 + 0], s);
            atomicAdd(&stats_out[og * 2 + 1], q);
        }
    }
}

// ---------------- cp.async staging helper ------------------------------------
// stages 2 (c-halves) x 9 (ij) rows x 128 floats for step s into inbuf[bi]
template <int C, int HIN, int OH>
static __device__ __forceinline__ void stage_step(const float* __restrict__ in,
                                                  float* __restrict__ inbuf, int bi,
                                                  int s, int y, int x, int b_blk, int tid) {
    constexpr int CCH = C / 2;
#pragma unroll
    for (int it = 0; it < 5; ++it) {
        int ch = tid + it * 128;
        if (ch < 576) {
            int x16 = ch & 31;
            int ij  = (ch >> 5) % 9;
            int cs  = ch / 288;
            int cg  = cs * CCH + s;
            int i = ij / 3, j = ij % 3;
            const float* g = in + ((size_t)cg * HIN * HIN + (size_t)(y + i) * HIN + (x + j)) * 1024
                             + b_blk + x16 * 4;
            float* dsm = inbuf + (((bi * 2 + cs) * 9) + ij) * 128 + x16 * 4;
            uint32_t sa = (uint32_t)__cvta_generic_to_shared(dsm);
            asm volatile("cp.async.cg.shared.global [%0], [%1], 16;" :: "r"(sa), "l"(g));
        }
    }
}

// ---------------- LC with cp.async double-buffered input staging -------------
// block (32,4): ogrp = w&1 (16 outputs), wsplit = w>>1 (k halves). batch 128.
// grid (OH*OH, 8, O_TOT/16)
template <int C, int HIN, int OH, int O_TOT, int MINB>
__global__ void __launch_bounds__(128, MINB)
lc_async_kernel(const float* __restrict__ in, const float* __restrict__ WT,
                const float* __restrict__ bias, float* __restrict__ out,
                float* __restrict__ stats_out) {
    constexpr int KK  = C * 9;
    constexpr int CCH = C / 2;
    constexpr int C10 = C * 10;

    const int loc    = blockIdx.x;
    const int y      = loc / OH, x = loc % OH;
    const int o_base = blockIdx.z * 16;
    const int lane   = threadIdx.x;
    const int w      = threadIdx.y;
    const int ogrp   = w & 1, wsplit = w >> 1;
    const int tid    = w * 32 + lane;
    const int b_blk  = blockIdx.y * 128;
    const int b0     = b_blk + lane * 2;

    extern __shared__ __align__(16) unsigned char smraw[];
    ull*   Ws2   = (ull*)smraw;                  // [16][C10] duplicated-packed
    float* inbuf = (float*)(Ws2 + 16 * C10);     // [2][2][9][128]

    const float* wsrc = WT + ((size_t)loc * O_TOT + o_base) * KK;
    for (int lin = tid; lin < 16 * KK; lin += 128) {
        int o = lin / KK, k = lin - o * KK;
        float wv = wsrc[lin];
        Ws2[o * C10 + (k / 9) * 10 + (k % 9)] = pk2(wv, wv);
    }

    stage_step<C, HIN, OH>(in, inbuf, 0, 0, y, x, b_blk, tid);
    asm volatile("cp.async.commit_group;");

    ull acc[8][2];
#pragma unroll
    for (int o = 0; o < 8; o++) { acc[o][0] = 0ull; acc[o][1] = 0ull; }

    const ull* wp = Ws2 + (ogrp * 8) * C10;

    for (int s = 0; s < CCH; ++s) {
        asm volatile("cp.async.wait_group 0;");
        __syncthreads();                          // buf[s&1] visible; buf[(s+1)&1] free
        if (s + 1 < CCH) {
            stage_step<C, HIN, OH>(in, inbuf, (s + 1) & 1, s + 1, y, x, b_blk, tid);
            asm volatile("cp.async.commit_group;");
        }
        const float* ib = inbuf + (((s & 1) * 2 + wsplit) * 9) * 128;
        const int cc = wsplit * CCH + s;
#pragma unroll
        for (int p = 0; p < 4; ++p) {
            const float* r0 = ib + (2 * p) * 128;
            const float* r1 = ib + (2 * p + 1) * 128;
            ull u0 = *(const ull*)(r0 + lane * 2);
            ull u1 = *(const ull*)(r0 + 64 + lane * 2);
            ull t0 = *(const ull*)(r1 + lane * 2);
            ull t1 = *(const ull*)(r1 + 64 + lane * 2);
#pragma unroll
            for (int o = 0; o < 8; ++o) {
                ulonglong2 wv = *(const ulonglong2*)&wp[o * C10 + cc * 10 + 2 * p];
                acc[o][0] = f2fma(u0, wv.x, acc[o][0]);
                acc[o][1] = f2fma(u1, wv.x, acc[o][1]);
                acc[o][0] = f2fma(t0, wv.y, acc[o][0]);
                acc[o][1] = f2fma(t1, wv.y, acc[o][1]);
            }
        }
        {
            const float* r8 = ib + 8 * 128;
            ull u0 = *(const ull*)(r8 + lane * 2);
            ull u1 = *(const ull*)(r8 + 64 + lane * 2);
#pragma unroll
            for (int o = 0; o < 8; ++o) {
                ull wv = wp[o * C10 + cc * 10 + 8];
                acc[o][0] = f2fma(u0, wv, acc[o][0]);
                acc[o][1] = f2fma(u1, wv, acc[o][1]);
            }
        }
    }

    // k-split reduction through smem overlay on inbuf
    __syncthreads();
    ull* red = (ull*)inbuf;
    if (wsplit == 1) {
#pragma unroll
        for (int o = 0; o < 8; ++o) {
            red[(((ogrp * 8 + o) * 2 + 0) * 32) + lane] = acc[o][0];
            red[(((ogrp * 8 + o) * 2 + 1) * 32) + lane] = acc[o][1];
        }
    }
    __syncthreads();
    if (wsplit == 1) return;
#pragma unroll
    for (int o = 0; o < 8; ++o) {
        acc[o][0] = f2add(acc[o][0], red[(((ogrp * 8 + o) * 2 + 0) * 32) + lane]);
        acc[o][1] = f2add(acc[o][1], red[(((ogrp * 8 + o) * 2 + 1) * 32) + lane]);
    }

    // bias + store pre-BN + per-channel BN stats
#pragma unroll
    for (int o = 0; o < 8; ++o) {
        int og = o_base + ogrp * 8 + o;
        float bb = __ldg(&bias[og * OH * OH + loc]);
        ull b2 = pk2(bb, bb);
        float* op = out + ((size_t)og * OH * OH + loc) * 1024 + b0;
        ull r0 = f2add(acc[o][0], b2);
        ull r1 = f2add(acc[o][1], b2);
        *(ull*)op = r0;
        *(ull*)(op + 64) = r1;
        ull s2 = f2add(r0, r1);
        ull q2 = f2fma(r1, r1, f2fma(r0, r0, 0ull));
        float sl, sh, ql, qh;
        upk2(s2, sl, sh); upk2(q2, ql, qh);
        float s = sl + sh, q = ql + qh;
#pragma unroll
        for (int off = 16; off > 0; off >>= 1) {
            s += __shfl_down_sync(0xffffffffu, s, off);
            q += __shfl_down_sync(0xffffffffu, q, off);
        }
        if (lane == 0) {
            atomicAdd(&stats_out[og * 2 + 0], s);
            atomicAdd(&stats_out[og * 2 + 1], q);
        }
    }
}

// ---------------- BN apply + ReLU, in place ----------------------------------
__global__ void bn_relu_kernel(const float* __restrict__ stats, const float* __restrict__ g,
                               const float* __restrict__ be, float* __restrict__ data,
                               int per_chan, float inv_n) {
    int ch = blockIdx.y;
    float m  = stats[ch * 2 + 0] * inv_n;
    float v  = stats[ch * 2 + 1] * inv_n - m * m;
    float sc = g[ch] * rsqrtf(v + EPSV);
    float sh = be[ch] - sc * m;
    float4* p = (float4*)(data + (size_t)ch * per_chan);
    int i = blockIdx.x * blockDim.x + threadIdx.x;
    float4 t = p[i];
    t.x = fmaxf(fmaf(t.x, sc, sh), 0.f);
    t.y = fmaxf(fmaf(t.y, sc, sh), 0.f);
    t.z = fmaxf(fmaf(t.z, sc, sh), 0.f);
    t.w = fmaxf(fmaf(t.w, sc, sh), 0.f);
    p[i] = t;
}

// ---------------- FC with fused BN3 + tanh -----------------------------------
__global__ void fc_partial_kernel(const float* __restrict__ h, const float* __restrict__ Wfc,
                                  const float* __restrict__ stats, const float* __restrict__ g,
                                  const float* __restrict__ be, float inv_n) {
    const int FCH = 256;
    int b  = blockIdx.x * 128 + threadIdx.x;
    int f0 = blockIdx.y * FCH;
    __shared__ float Wsm[10 * FCH];
    __shared__ float fsc[FCH], fsh[FCH];
    for (int i = threadIdx.x; i < 10 * FCH; i += 128) {
        int t = i / FCH, f = i % FCH;
        Wsm[i] = Wfc[t * 6400 + f0 + f];
    }
    for (int f = threadIdx.x; f < FCH; f += 128) {
        int ch = (f0 + f) / 100;
        float m  = stats[ch * 2 + 0] * inv_n;
        float v  = stats[ch * 2 + 1] * inv_n - m * m;
        float sc = g[ch] * rsqrtf(v + EPSV);
        fsc[f] = sc;
        fsh[f] = be[ch] - sc * m;
    }
    __syncthreads();
    float acc[10];
#pragma unroll
    for (int t = 0; t < 10; t++) acc[t] = 0.f;
    for (int f = 0; f < FCH; f++) {
        float v = h[(size_t)(f0 + f) * 1024 + b];
        v = tanhf(fmaf(v, fsc[f], fsh[f]));
#pragma unroll
        for (int t = 0; t < 10; t++) acc[t] = fmaf(v, Wsm[t * FCH + f], acc[t]);
    }
#pragma unroll
    for (int t = 0; t < 10; t++)
        g_part[((size_t)blockIdx.y * 10 + t) * 1024 + b] = acc[t];
}

__global__ void fc_reduce_kernel(const float* __restrict__ fcb, float* __restrict__ out) {
    int idx = blockIdx.x * blockDim.x + threadIdx.x;
    if (idx >= 10240) return;
    int b = idx / 10, t = idx % 10;
    float s = fcb[t];
#pragma unroll
    for (int c = 0; c < 25; c++) s += g_part[((size_t)c * 10 + t) * 1024 + b];
    out[b * 10 + t] = s;
}

// ---------------- launch -----------------------------------------------------
extern "C" void kernel_launch(void* const* d_in, const int* in_sizes, int n_in,
                              void* d_out, int out_size) {
    const float* x   = (const float*)d_in[0];
    const float* W1  = (const float*)d_in[1];
    const float* b1  = (const float*)d_in[2];
    const float* g1  = (const float*)d_in[3];
    const float* be1 = (const float*)d_in[4];
    const float* W2  = (const float*)d_in[5];
    const float* b2  = (const float*)d_in[6];
    const float* g2  = (const float*)d_in[7];
    const float* be2 = (const float*)d_in[8];
    const float* W3  = (const float*)d_in[9];
    const float* b3  = (const float*)d_in[10];
    const float* g3  = (const float*)d_in[11];
    const float* be3 = (const float*)d_in[12];
    const float* fcW = (const float*)d_in[13];
    const float* fcb = (const float*)d_in[14];
    float* out = (float*)d_out;

    float *p_xt, *p_h1, *p_h2, *p_h3, *p_stats, *p_w1t, *p_w2t, *p_w3t;
    cudaGetSymbolAddress((void**)&p_xt, g_xt);
    cudaGetSymbolAddress((void**)&p_h1, g_h1);
    cudaGetSymbolAddress((void**)&p_h2, g_h2);
    cudaGetSymbolAddress((void**)&p_h3, g_h3);
    cudaGetSymbolAddress((void**)&p_stats, g_stats);
    cudaGetSymbolAddress((void**)&p_w1t, g_w1t);
    cudaGetSymbolAddress((void**)&p_w2t, g_w2t);
    cudaGetSymbolAddress((void**)&p_w3t, g_w3t);

    const int sm1 = 16 * 1 * 10 * 8;                       // 1.28 KB
    const int sm2 = 16 * 16 * 10 * 8 + 2 * 2 * 9 * 128 * 4;  // 20.5 + 18.4 KB
    const int sm3 = 16 * 32 * 10 * 8 + 2 * 2 * 9 * 128 * 4;  // 41 + 18.4 KB
    cudaFuncSetAttribute((const void*)lc_small_kernel<1, 16, 14, 16, 8>,
                         cudaFuncAttributeMaxDynamicSharedMemorySize, sm1);
    cudaFuncSetAttribute((const void*)lc_async_kernel<16, 14, 12, 32, 5>,
                         cudaFuncAttributeMaxDynamicSharedMemorySize, sm2);
    cudaFuncSetAttribute((const void*)lc_async_kernel<32, 12, 10, 64, 3>,
                         cudaFuncAttributeMaxDynamicSharedMemorySize, sm3);

    int wblocks = 257 + (28224 + 663552 + 1843200 + 255) / 256;
    prep_kernel<<<wblocks, 256>>>(x, W1, W2, W3);

    // #1 LC1, #2 bn1, #3 LC2 (profiled slot)
    lc_small_kernel<1, 16, 14, 16, 8><<<dim3(196, 4, 1), dim3(32, 2), sm1>>>(
        p_xt, p_w1t, b1, p_h1, p_stats + 0);
    bn_relu_kernel<<<dim3(196, 16), 256>>>(p_stats + 0, g1, be1, p_h1,
                                           14 * 14 * 1024, 1.f / (14.f * 14.f * 1024.f));
    lc_async_kernel<16, 14, 12, 32, 5><<<dim3(144, 8, 2), dim3(32, 4), sm2>>>(
        p_h1, p_w2t, b2, p_h2, p_stats + 32);
    bn_relu_kernel<<<dim3(144, 32), 256>>>(p_stats + 32, g2, be2, p_h2,
                                           12 * 12 * 1024, 1.f / (12.f * 12.f * 1024.f));
    lc_async_kernel<32, 12, 10, 64, 3><<<dim3(100, 8, 4), dim3(32, 4), sm3>>>(
        p_h2, p_w3t, b3, p_h3, p_stats + 96);

    fc_partial_kernel<<<dim3(8, 25), 128>>>(p_h3, fcW, p_stats + 96, g3, be3,
                                            1.f / (10.f * 10.f * 1024.f));
    fc_reduce_kernel<<<40, 256>>>(fcb, out);
}

// round 7
// speedup vs baseline: 1.0489x; 1.0489x over previous
#include <cuda_runtime.h>
#include <math.h>
#include <stdint.h>

#define EPSV 1e-5f
typedef unsigned long long ull;

// ---------------- f32x2 helpers ---------------------------------------------
static __device__ __forceinline__ ull pk2(float lo, float hi) {
    ull r; asm("mov.b64 %0,{%1,%2};" : "=l"(r) : "f"(lo), "f"(hi)); return r;
}
static __device__ __forceinline__ void upk2(ull v, float& lo, float& hi) {
    asm("mov.b64 {%0,%1},%2;" : "=f"(lo), "=f"(hi) : "l"(v));
}
static __device__ __forceinline__ ull f2fma(ull a, ull b, ull c) {
    ull r; asm("fma.rn.f32x2 %0,%1,%2,%3;" : "=l"(r) : "l"(a), "l"(b), "l"(c)); return r;
}
static __device__ __forceinline__ ull f2add(ull a, ull b) {
    ull r; asm("add.rn.f32x2 %0,%1,%2;" : "=l"(r) : "l"(a), "l"(b)); return r;
}

// ---------------- scratch ----------------------------------------------------
__device__ float g_xt[1 * 16 * 16 * 1024];
__device__ float g_h1[16 * 14 * 14 * 1024];
__device__ float g_h2[32 * 12 * 12 * 1024];
__device__ float g_h3[64 * 10 * 10 * 1024];          // pre-BN (BN3 fused in FC)
__device__ float g_stats[224];
__device__ float g_part[25 * 10 * 1024];
__device__ float g_w1t[196 * 16 * 9];
__device__ float g_w2t[144 * 32 * 144];
__device__ float g_w3t[100 * 64 * 288];

// ---------------- fused prep: transpose x + zero stats + weight reorder -----
__global__ void prep_kernel(const float* __restrict__ x,
                            const float* __restrict__ W1,
                            const float* __restrict__ W2,
                            const float* __restrict__ W3) {
    int bid = blockIdx.x;
    if (bid < 256) {
        __shared__ float tile[32][33];
        int bx = bid % 8, by = bid / 8;
        int tx = threadIdx.x % 32, ty = threadIdx.x / 32;
        for (int r = 0; r < 4; r++) {
            int p = bx * 32 + tx;
            int b = by * 32 + ty + r * 8;
            tile[ty + r * 8][tx] = x[b * 256 + p];
        }
        __syncthreads();
        for (int r = 0; r < 4; r++) {
            int p2 = bx * 32 + ty + r * 8;
            int b2 = by * 32 + tx;
            g_xt[p2 * 1024 + b2] = tile[tx][ty + r * 8];
        }
        return;
    }
    if (bid == 256) {
        if (threadIdx.x < 224) g_stats[threadIdx.x] = 0.f;
        return;
    }
    long idx = (long)(bid - 257) * 256 + threadIdx.x;
    if (idx < 28224) {
        int k = idx % 9, o = (idx / 9) % 16, loc = idx / (9 * 16);
        g_w1t[idx] = W1[(((o * 1) * 14 + loc / 14) * 14 + loc % 14) * 9 + k];
        return;
    }
    idx -= 28224;
    if (idx < 663552) {
        int k = idx % 144, o = (idx / 144) % 32, loc = idx / (144 * 32);
        int c = k / 9, ij = k % 9;
        g_w2t[idx] = W2[((((o * 16 + c) * 12 + loc / 12) * 12 + loc % 12)) * 9 + ij];
        return;
    }
    idx -= 663552;
    if (idx < 1843200) {
        int k = idx % 288, o = (idx / 288) % 64, loc = idx / (288 * 64);
        int c = k / 9, ij = k % 9;
        g_w3t[idx] = W3[((((o * 32 + c) * 10 + loc / 10) * 10 + loc % 10)) * 9 + ij];
    }
}

// ---------------- LC1 (C=1): round-5 direct-LDG version ----------------------
template <int C, int HIN, int OH, int O_TOT, int MINB>
__global__ void __launch_bounds__(64, MINB)
lc_small_kernel(const float* __restrict__ in, const float* __restrict__ WT,
                const float* __restrict__ bias, float* __restrict__ out,
                float* __restrict__ stats_out) {
    constexpr int KK  = C * 9;
    constexpr int C10 = C * 10;

    const int loc    = blockIdx.x;
    const int o_base = blockIdx.z * 16;
    const int lane   = threadIdx.x;
    const int b0     = blockIdx.y * 256 + lane * 2;
    const int tid    = threadIdx.y * 32 + lane;
    const int ogrp   = threadIdx.y;

    extern __shared__ __align__(16) unsigned char smraw[];
    ull* Ws2 = (ull*)smraw;

    const float* wsrc = WT + ((size_t)loc * O_TOT + o_base) * KK;
    for (int lin = tid; lin < 16 * KK; lin += 64) {
        int o = lin / KK, k = lin % KK;
        float w = wsrc[lin];
        Ws2[o * C10 + (k / 9) * 10 + (k % 9)] = pk2(w, w);
    }
    __syncthreads();

    ull acc[8][4];
#pragma unroll
    for (int o = 0; o < 8; o++)
#pragma unroll
        for (int m = 0; m < 4; m++) acc[o][m] = 0ull;

    const ull* wp = Ws2 + ogrp * 8 * C10;
    const float* cp = in + ((size_t)(loc / OH) * HIN + (loc % OH)) * 1024 + b0;

    for (int c = 0; c < C; c++) {
#pragma unroll
        for (int p = 0; p < 4; p++) {
            const int ij0 = 2 * p, ij1 = 2 * p + 1;
            const int off0 = ((ij0 / 3) * HIN + (ij0 % 3)) * 1024;
            const int off1 = ((ij1 / 3) * HIN + (ij1 % 3)) * 1024;
            ull v0[4], v1[4];
#pragma unroll
            for (int m = 0; m < 4; m++) v0[m] = *(const ull*)(cp + off0 + 64 * m);
#pragma unroll
            for (int m = 0; m < 4; m++) v1[m] = *(const ull*)(cp + off1 + 64 * m);
#pragma unroll
            for (int o = 0; o < 8; o++) {
                ulonglong2 w = *(const ulonglong2*)&wp[o * C10 + c * 10 + 2 * p];
#pragma unroll
                for (int m = 0; m < 4; m++) acc[o][m] = f2fma(v0[m], w.x, acc[o][m]);
#pragma unroll
                for (int m = 0; m < 4; m++) acc[o][m] = f2fma(v1[m], w.y, acc[o][m]);
            }
        }
        {
            const int off = (2 * HIN + 2) * 1024;
            ull v[4];
#pragma unroll
            for (int m = 0; m < 4; m++) v[m] = *(const ull*)(cp + off + 64 * m);
#pragma unroll
            for (int o = 0; o < 8; o++) {
                ull w2 = wp[o * C10 + c * 10 + 8];
#pragma unroll
                for (int m = 0; m < 4; m++) acc[o][m] = f2fma(v[m], w2, acc[o][m]);
            }
        }
        cp += HIN * HIN * 1024;
    }

#pragma unroll
    for (int o = 0; o < 8; o++) {
        int og = o_base + ogrp * 8 + o;
        float bb = __ldg(&bias[og * OH * OH + loc]);
        ull b2 = pk2(bb, bb);
        float* op = out + ((size_t)og * OH * OH + loc) * 1024 + b0;
        ull s2 = 0ull, q2 = 0ull;
#pragma unroll
        for (int m = 0; m < 4; m++) {
            ull r = f2add(acc[o][m], b2);
            *(ull*)(op + 64 * m) = r;
            s2 = f2add(s2, r);
            q2 = f2fma(r, r, q2);
        }
        float sl, sh, ql, qh;
        upk2(s2, sl, sh); upk2(q2, ql, qh);
        float s = sl + sh, q = ql + qh;
#pragma unroll
        for (int off = 16; off > 0; off >>= 1) {
            s += __shfl_down_sync(0xffffffffu, s, off);
            q += __shfl_down_sync(0xffffffffu, q, off);
        }
        if (lane == 0) {
            atomicAdd(&stats_out[og * 2 + 0], s);
            atomicAdd(&stats_out[og * 2 + 1], q);
        }
    }
}

// ---------------- LC with explicit register prefetch -------------------------
// SPLIT=0: 4 warps = 2 ogrps x 2 batch-halves (block: 16 o x 256 b)
// SPLIT=1: 4 warps = 2 ogrps x 2 k-halves    (block: 16 o x 128 b), smem-overlay reduce
// grid (OH*OH, grid_y, O_TOT/16)
template <int C, int HIN, int OH, int O_TOT, int SPLIT, int MINB>
__global__ void __launch_bounds__(128, MINB)
lc_pf_kernel(const float* __restrict__ in, const float* __restrict__ WT,
             const float* __restrict__ bias, float* __restrict__ out,
             float* __restrict__ stats_out) {
    constexpr int KK  = C * 9;
    constexpr int C10 = C * 10;
    constexpr int CH  = HIN * HIN * 1024;
    constexpr int CCH = SPLIT ? C / 2 : C;

    const int loc    = blockIdx.x;
    const int y      = loc / OH, x = loc % OH;
    const int o_base = blockIdx.z * 16;
    const int lane   = threadIdx.x;
    const int w      = threadIdx.y;
    const int ogrp   = w & 1;
    const int ws     = w >> 1;                 // batch-half (SPLIT=0) or k-half (SPLIT=1)
    const int tid    = w * 32 + lane;
    const int b0     = SPLIT ? (blockIdx.y * 128 + lane * 2)
                             : (blockIdx.y * 256 + ws * 128 + lane * 2);

    extern __shared__ __align__(16) unsigned char smraw[];
    ull* Ws2 = (ull*)smraw;                    // [16][C10] duplicated-packed

    const float* wsrc = WT + ((size_t)loc * O_TOT + o_base) * KK;
    for (int lin = tid; lin < 16 * KK; lin += 128) {
        int o = lin / KK, k = lin - o * KK;
        float wv = wsrc[lin];
        Ws2[o * C10 + (k / 9) * 10 + (k % 9)] = pk2(wv, wv);
    }
    __syncthreads();

    ull acc[8][2];
#pragma unroll
    for (int o = 0; o < 8; o++) { acc[o][0] = 0ull; acc[o][1] = 0ull; }

    const ull* wp2 = Ws2 + (ogrp * 8) * C10 + (SPLIT ? ws * CCH * 10 : 0);
    const float* cp = in + ((size_t)(SPLIT ? ws * CCH : 0) * HIN * HIN
                            + (size_t)y * HIN + x) * 1024 + b0;

#define LD4(BASE, IJ) do { \
    const float* _p0 = (BASE) + (((IJ) / 3) * HIN + ((IJ) % 3)) * 1024; \
    const float* _p1 = (BASE) + ((((IJ) + 1) / 3) * HIN + (((IJ) + 1) % 3)) * 1024; \
    na0 = *(const ull*)_p0; na1 = *(const ull*)(_p0 + 64); \
    nb0 = *(const ull*)_p1; nb1 = *(const ull*)(_p1 + 64); } while (0)

#define FMAP(CI, PK) do { \
    _Pragma("unroll") \
    for (int o = 0; o < 8; o++) { \
        ulonglong2 wv = *(const ulonglong2*)&wp2[o * C10 + (CI) * 10 + 2 * (PK)]; \
        acc[o][0] = f2fma(ca0, wv.x, acc[o][0]); \
        acc[o][1] = f2fma(ca1, wv.x, acc[o][1]); \
        acc[o][0] = f2fma(cb0, wv.y, acc[o][0]); \
        acc[o][1] = f2fma(cb1, wv.y, acc[o][1]); } } while (0)

#define ROT() do { ca0 = na0; ca1 = na1; cb0 = nb0; cb1 = nb1; } while (0)

    ull ca0, ca1, cb0, cb1, na0, na1, nb0, nb1;
    LD4(cp, 0); ROT();

    for (int c = 0; c < CCH; c++) {
        const float* nxt = (c + 1 < CCH) ? cp + CH : cp;
        LD4(cp, 2); FMAP(c, 0); ROT();
        LD4(cp, 4); FMAP(c, 1); ROT();
        LD4(cp, 6); FMAP(c, 2); ROT();
        ull s0, s1;
        {   // prefetch singleton (ij=8)
            const float* p8 = cp + (2 * HIN + 2) * 1024;
            s0 = *(const ull*)p8; s1 = *(const ull*)(p8 + 64);
        }
        FMAP(c, 3);
        LD4(nxt, 0);                        // prefetch next-c pair0 during singleton FMAs
#pragma unroll
        for (int o = 0; o < 8; o++) {
            ull wv = wp2[o * C10 + c * 10 + 8];
            acc[o][0] = f2fma(s0, wv, acc[o][0]);
            acc[o][1] = f2fma(s1, wv, acc[o][1]);
        }
        ROT();
        cp = nxt;
    }
#undef LD4
#undef FMAP
#undef ROT

    if (SPLIT) {   // k-split reduction through smem overlay on weights
        __syncthreads();                       // all weight reads done
        ull* red = (ull*)smraw;                // [ogrp*8+o][m][lane]
        if (ws == 1) {
#pragma unroll
            for (int o = 0; o < 8; o++) {
                red[(((ogrp * 8 + o) * 2 + 0) * 32) + lane] = acc[o][0];
                red[(((ogrp * 8 + o) * 2 + 1) * 32) + lane] = acc[o][1];
            }
        }
        __syncthreads();
        if (ws == 1) return;
#pragma unroll
        for (int o = 0; o < 8; o++) {
            acc[o][0] = f2add(acc[o][0], red[(((ogrp * 8 + o) * 2 + 0) * 32) + lane]);
            acc[o][1] = f2add(acc[o][1], red[(((ogrp * 8 + o) * 2 + 1) * 32) + lane]);
        }
    }

    // bias + store pre-BN + per-channel BN stats
#pragma unroll
    for (int o = 0; o < 8; o++) {
        int og = o_base + ogrp * 8 + o;
        float bb = __ldg(&bias[og * OH * OH + loc]);
        ull b2 = pk2(bb, bb);
        float* op = out + ((size_t)og * OH * OH + loc) * 1024 + b0;
        ull r0 = f2add(acc[o][0], b2);
        ull r1 = f2add(acc[o][1], b2);
        *(ull*)op = r0;
        *(ull*)(op + 64) = r1;
        ull s2 = f2add(r0, r1);
        ull q2 = f2fma(r1, r1, f2fma(r0, r0, 0ull));
        float sl, sh, ql, qh;
        upk2(s2, sl, sh); upk2(q2, ql, qh);
        float s = sl + sh, q = ql + qh;
#pragma unroll
        for (int off = 16; off > 0; off >>= 1) {
            s += __shfl_down_sync(0xffffffffu, s, off);
            q += __shfl_down_sync(0xffffffffu, q, off);
        }
        if (lane == 0) {
            atomicAdd(&stats_out[og * 2 + 0], s);
            atomicAdd(&stats_out[og * 2 + 1], q);
        }
    }
}

// ---------------- BN apply + ReLU, in place ----------------------------------
__global__ void bn_relu_kernel(const float* __restrict__ stats, const float* __restrict__ g,
                               const float* __restrict__ be, float* __restrict__ data,
                               int per_chan, float inv_n) {
    int ch = blockIdx.y;
    float m  = stats[ch * 2 + 0] * inv_n;
    float v  = stats[ch * 2 + 1] * inv_n - m * m;
    float sc = g[ch] * rsqrtf(v + EPSV);
    float sh = be[ch] - sc * m;
    float4* p = (float4*)(data + (size_t)ch * per_chan);
    int i = blockIdx.x * blockDim.x + threadIdx.x;
    float4 t = p[i];
    t.x = fmaxf(fmaf(t.x, sc, sh), 0.f);
    t.y = fmaxf(fmaf(t.y, sc, sh), 0.f);
    t.z = fmaxf(fmaf(t.z, sc, sh), 0.f);
    t.w = fmaxf(fmaf(t.w, sc, sh), 0.f);
    p[i] = t;
}

// ---------------- FC with fused BN3 + tanh -----------------------------------
__global__ void fc_partial_kernel(const float* __restrict__ h, const float* __restrict__ Wfc,
                                  const float* __restrict__ stats, const float* __restrict__ g,
                                  const float* __restrict__ be, float inv_n) {
    const int FCH = 256;
    int b  = blockIdx.x * 128 + threadIdx.x;
    int f0 = blockIdx.y * FCH;
    __shared__ float Wsm[10 * FCH];
    __shared__ float fsc[FCH], fsh[FCH];
    for (int i = threadIdx.x; i < 10 * FCH; i += 128) {
        int t = i / FCH, f = i % FCH;
        Wsm[i] = Wfc[t * 6400 + f0 + f];
    }
    for (int f = threadIdx.x; f < FCH; f += 128) {
        int ch = (f0 + f) / 100;
        float m  = stats[ch * 2 + 0] * inv_n;
        float v  = stats[ch * 2 + 1] * inv_n - m * m;
        float sc = g[ch] * rsqrtf(v + EPSV);
        fsc[f] = sc;
        fsh[f] = be[ch] - sc * m;
    }
    __syncthreads();
    float acc[10];
#pragma unroll
    for (int t = 0; t < 10; t++) acc[t] = 0.f;
    for (int f = 0; f < FCH; f++) {
        float v = h[(size_t)(f0 + f) * 1024 + b];
        v = tanhf(fmaf(v, fsc[f], fsh[f]));
#pragma unroll
        for (int t = 0; t < 10; t++) acc[t] = fmaf(v, Wsm[t * FCH + f], acc[t]);
    }
#pragma unroll
    for (int t = 0; t < 10; t++)
        g_part[((size_t)blockIdx.y * 10 + t) * 1024 + b] = acc[t];
}

__global__ void fc_reduce_kernel(const float* __restrict__ fcb, float* __restrict__ out) {
    int idx = blockIdx.x * blockDim.x + threadIdx.x;
    if (idx >= 10240) return;
    int b = idx / 10, t = idx % 10;
    float s = fcb[t];
#pragma unroll
    for (int c = 0; c < 25; c++) s += g_part[((size_t)c * 10 + t) * 1024 + b];
    out[b * 10 + t] = s;
}

// ---------------- launch -----------------------------------------------------
extern "C" void kernel_launch(void* const* d_in, const int* in_sizes, int n_in,
                              void* d_out, int out_size) {
    const float* x   = (const float*)d_in[0];
    const float* W1  = (const float*)d_in[1];
    const float* b1  = (const float*)d_in[2];
    const float* g1  = (const float*)d_in[3];
    const float* be1 = (const float*)d_in[4];
    const float* W2  = (const float*)d_in[5];
    const float* b2  = (const float*)d_in[6];
    const float* g2  = (const float*)d_in[7];
    const float* be2 = (const float*)d_in[8];
    const float* W3  = (const float*)d_in[9];
    const float* b3  = (const float*)d_in[10];
    const float* g3  = (const float*)d_in[11];
    const float* be3 = (const float*)d_in[12];
    const float* fcW = (const float*)d_in[13];
    const float* fcb = (const float*)d_in[14];
    float* out = (float*)d_out;

    float *p_xt, *p_h1, *p_h2, *p_h3, *p_stats, *p_w1t, *p_w2t, *p_w3t;
    cudaGetSymbolAddress((void**)&p_xt, g_xt);
    cudaGetSymbolAddress((void**)&p_h1, g_h1);
    cudaGetSymbolAddress((void**)&p_h2, g_h2);
    cudaGetSymbolAddress((void**)&p_h3, g_h3);
    cudaGetSymbolAddress((void**)&p_stats, g_stats);
    cudaGetSymbolAddress((void**)&p_w1t, g_w1t);
    cudaGetSymbolAddress((void**)&p_w2t, g_w2t);
    cudaGetSymbolAddress((void**)&p_w3t, g_w3t);

    const int sm1 = 16 * 1 * 10 * 8;      // 1.28 KB
    const int sm2 = 16 * 16 * 10 * 8;     // 20.5 KB
    const int sm3 = 16 * 32 * 10 * 8;     // 41 KB
    cudaFuncSetAttribute((const void*)lc_small_kernel<1, 16, 14, 16, 8>,
                         cudaFuncAttributeMaxDynamicSharedMemorySize, sm1);
    cudaFuncSetAttribute((const void*)lc_pf_kernel<16, 14, 12, 32, 0, 6>,
                         cudaFuncAttributeMaxDynamicSharedMemorySize, sm2);
    cudaFuncSetAttribute((const void*)lc_pf_kernel<32, 12, 10, 64, 1, 5>,
                         cudaFuncAttributeMaxDynamicSharedMemorySize, sm3);

    int wblocks = 257 + (28224 + 663552 + 1843200 + 255) / 256;
    prep_kernel<<<wblocks, 256>>>(x, W1, W2, W3);

    // #1 LC1, #2 bn1, #3 LC2 (profiled slot)
    lc_small_kernel<1, 16, 14, 16, 8><<<dim3(196, 4, 1), dim3(32, 2), sm1>>>(
        p_xt, p_w1t, b1, p_h1, p_stats + 0);
    bn_relu_kernel<<<dim3(196, 16), 256>>>(p_stats + 0, g1, be1, p_h1,
                                           14 * 14 * 1024, 1.f / (14.f * 14.f * 1024.f));
    lc_pf_kernel<16, 14, 12, 32, 0, 6><<<dim3(144, 4, 2), dim3(32, 4), sm2>>>(
        p_h1, p_w2t, b2, p_h2, p_stats + 32);
    bn_relu_kernel<<<dim3(144, 32), 256>>>(p_stats + 32, g2, be2, p_h2,
                                           12 * 12 * 1024, 1.f / (12.f * 12.f * 1024.f));
    lc_pf_kernel<32, 12, 10, 64, 1, 5><<<dim3(100, 8, 4), dim3(32, 4), sm3>>>(
        p_h2, p_w3t, b3, p_h3, p_stats + 96);

    fc_partial_kernel<<<dim3(8, 25), 128>>>(p_h3, fcW, p_stats + 96, g3, be3,
                                            1.f / (10.f * 10.f * 1024.f));
    fc_reduce_kernel<<<40, 256>>>(fcb, out);
}

// round 8
// speedup vs baseline: 1.1149x; 1.0630x over previous
#include <cuda_runtime.h>
#include <math.h>
#include <stdint.h>

#define EPSV 1e-5f
typedef unsigned long long ull;

// ---------------- f32x2 helpers ---------------------------------------------
static __device__ __forceinline__ ull pk2(float lo, float hi) {
    ull r; asm("mov.b64 %0,{%1,%2};" : "=l"(r) : "f"(lo), "f"(hi)); return r;
}
static __device__ __forceinline__ void upk2(ull v, float& lo, float& hi) {
    asm("mov.b64 {%0,%1},%2;" : "=f"(lo), "=f"(hi) : "l"(v));
}
static __device__ __forceinline__ ull f2fma(ull a, ull b, ull c) {
    ull r; asm("fma.rn.f32x2 %0,%1,%2,%3;" : "=l"(r) : "l"(a), "l"(b), "l"(c)); return r;
}
static __device__ __forceinline__ ull f2add(ull a, ull b) {
    ull r; asm("add.rn.f32x2 %0,%1,%2;" : "=l"(r) : "l"(a), "l"(b)); return r;
}

// ---------------- scratch ----------------------------------------------------
__device__ float g_xt[1 * 16 * 16 * 1024];
__device__ float g_h1[16 * 14 * 14 * 1024];
__device__ float g_h2[32 * 12 * 12 * 1024];
__device__ float g_h3[64 * 10 * 10 * 1024];          // pre-BN (BN3 fused in FC)
__device__ float g_stats[224];
__device__ float g_part[25 * 10 * 1024];
// transposed weights: T[loc][o][k], k = c*9+ij
__device__ float g_w1t[196 * 16 * 9];
__device__ float g_w2t[144 * 32 * 144];
__device__ float g_w3t[100 * 64 * 288];

// ---------------- fused prep: transpose x + zero stats + weight reorder -----
__global__ void prep_kernel(const float* __restrict__ x,
                            const float* __restrict__ W1,
                            const float* __restrict__ W2,
                            const float* __restrict__ W3) {
    int bid = blockIdx.x;
    if (bid < 256) {
        __shared__ float tile[32][33];
        int bx = bid % 8, by = bid / 8;
        int tx = threadIdx.x % 32, ty = threadIdx.x / 32;
        for (int r = 0; r < 4; r++) {
            int p = bx * 32 + tx;
            int b = by * 32 + ty + r * 8;
            tile[ty + r * 8][tx] = x[b * 256 + p];
        }
        __syncthreads();
        for (int r = 0; r < 4; r++) {
            int p2 = bx * 32 + ty + r * 8;
            int b2 = by * 32 + tx;
            g_xt[p2 * 1024 + b2] = tile[tx][ty + r * 8];
        }
        return;
    }
    if (bid == 256) {
        if (threadIdx.x < 224) g_stats[threadIdx.x] = 0.f;
        return;
    }
    long idx = (long)(bid - 257) * 256 + threadIdx.x;
    if (idx < 28224) {
        int k = idx % 9, o = (idx / 9) % 16, loc = idx / (9 * 16);
        g_w1t[idx] = W1[(((o * 1) * 14 + loc / 14) * 14 + loc % 14) * 9 + k];
        return;
    }
    idx -= 28224;
    if (idx < 663552) {
        int k = idx % 144, o = (idx / 144) % 32, loc = idx / (144 * 32);
        int c = k / 9, ij = k % 9;
        g_w2t[idx] = W2[((((o * 16 + c) * 12 + loc / 12) * 12 + loc % 12)) * 9 + ij];
        return;
    }
    idx -= 663552;
    if (idx < 1843200) {
        int k = idx % 288, o = (idx / 288) % 64, loc = idx / (288 * 64);
        int c = k / 9, ij = k % 9;
        g_w3t[idx] = W3[((((o * 32 + c) * 10 + loc / 10) * 10 + loc % 10)) * 9 + ij];
    }
}

// ---------------- locally-connected layer, round-5 mainloop + k-halved smem --
// in (C,HIN,HIN,1024) post-BN; WT[loc][o][k]; out (O_TOT,OH,OH,1024) pre-BN
// block (32,2): warp = 8 outputs x 256 batch (MB2=4)
// KH: number of staged k-halves (1 = round-5 behavior; 2 halves smem for LC3)
// grid (OH*OH, 4, O_TOT/16)
template <int C, int HIN, int OH, int O_TOT, int KH, int MINB>
__global__ void __launch_bounds__(64, MINB)
lc_kernel(const float* __restrict__ in, const float* __restrict__ WT,
          const float* __restrict__ bias, float* __restrict__ out,
          float* __restrict__ stats_out) {
    constexpr int KK   = C * 9;          // total k per output
    constexpr int CCH  = C / KH;         // channels per staged half
    constexpr int KKH  = CCH * 9;        // k per half
    constexpr int C10H = CCH * 10;       // padded k-extent in smem per half

    const int loc    = blockIdx.x;
    const int o_base = blockIdx.z * 16;
    const int lane   = threadIdx.x;
    const int b0     = blockIdx.y * 256 + lane * 2;
    const int tid    = threadIdx.y * 32 + lane;
    const int ogrp   = threadIdx.y;

    extern __shared__ __align__(16) unsigned char smraw[];
    ull* Ws2 = (ull*)smraw;              // [o(16)][cch][10] duplicated-packed

    ull acc[8][4];
#pragma unroll
    for (int o = 0; o < 8; o++)
#pragma unroll
        for (int m = 0; m < 4; m++) acc[o][m] = 0ull;

    const float* cp = in + ((size_t)(loc / OH) * HIN + (loc % OH)) * 1024 + b0;

#pragma unroll 1
    for (int h = 0; h < KH; h++) {
        // stage this k-half's weights (coalesced from WT)
        if (h > 0) __syncthreads();      // previous half's reads complete
        const float* wsrc = WT + ((size_t)loc * O_TOT + o_base) * KK + h * KKH;
        for (int lin = tid; lin < 16 * KKH; lin += 64) {
            int o = lin / KKH, k = lin - o * KKH;
            float w = wsrc[(size_t)o * KK + k];
            Ws2[o * C10H + (k / 9) * 10 + (k % 9)] = pk2(w, w);
        }
        __syncthreads();

        const ull* wp = Ws2 + ogrp * 8 * C10H;
#pragma unroll 1
        for (int c = 0; c < CCH; c++) {
#pragma unroll
            for (int p = 0; p < 4; p++) {
                const int ij0 = 2 * p, ij1 = 2 * p + 1;
                const int off0 = ((ij0 / 3) * HIN + (ij0 % 3)) * 1024;
                const int off1 = ((ij1 / 3) * HIN + (ij1 % 3)) * 1024;
                ull v0[4], v1[4];
#pragma unroll
                for (int m = 0; m < 4; m++) v0[m] = *(const ull*)(cp + off0 + 64 * m);
#pragma unroll
                for (int m = 0; m < 4; m++) v1[m] = *(const ull*)(cp + off1 + 64 * m);
#pragma unroll
                for (int o = 0; o < 8; o++) {
                    ulonglong2 w = *(const ulonglong2*)&wp[o * C10H + c * 10 + 2 * p];
#pragma unroll
                    for (int m = 0; m < 4; m++) acc[o][m] = f2fma(v0[m], w.x, acc[o][m]);
#pragma unroll
                    for (int m = 0; m < 4; m++) acc[o][m] = f2fma(v1[m], w.y, acc[o][m]);
                }
            }
            {   // singleton ij = 8 (i=2, j=2)
                const int off = (2 * HIN + 2) * 1024;
                ull v[4];
#pragma unroll
                for (int m = 0; m < 4; m++) v[m] = *(const ull*)(cp + off + 64 * m);
#pragma unroll
                for (int o = 0; o < 8; o++) {
                    ull w2 = wp[o * C10H + c * 10 + 8];
#pragma unroll
                    for (int m = 0; m < 4; m++) acc[o][m] = f2fma(v[m], w2, acc[o][m]);
                }
            }
            cp += HIN * HIN * 1024;
        }
    }

    // bias + store pre-BN + per-channel BN stats
#pragma unroll
    for (int o = 0; o < 8; o++) {
        int og = o_base + ogrp * 8 + o;
        float bb = __ldg(&bias[og * OH * OH + loc]);
        ull b2 = pk2(bb, bb);
        float* op = out + ((size_t)og * OH * OH + loc) * 1024 + b0;
        ull s2 = 0ull, q2 = 0ull;
#pragma unroll
        for (int m = 0; m < 4; m++) {
            ull r = f2add(acc[o][m], b2);
            *(ull*)(op + 64 * m) = r;
            s2 = f2add(s2, r);
            q2 = f2fma(r, r, q2);
        }
        float sl, sh, ql, qh;
        upk2(s2, sl, sh); upk2(q2, ql, qh);
        float s = sl + sh, q = ql + qh;
#pragma unroll
        for (int off = 16; off > 0; off >>= 1) {
            s += __shfl_down_sync(0xffffffffu, s, off);
            q += __shfl_down_sync(0xffffffffu, q, off);
        }
        if (lane == 0) {
            atomicAdd(&stats_out[og * 2 + 0], s);
            atomicAdd(&stats_out[og * 2 + 1], q);
        }
    }
}

// ---------------- BN apply + ReLU, in place ----------------------------------
__global__ void bn_relu_kernel(const float* __restrict__ stats, const float* __restrict__ g,
                               const float* __restrict__ be, float* __restrict__ data,
                               int per_chan, float inv_n) {
    int ch = blockIdx.y;
    float m  = stats[ch * 2 + 0] * inv_n;
    float v  = stats[ch * 2 + 1] * inv_n - m * m;
    float sc = g[ch] * rsqrtf(v + EPSV);
    float sh = be[ch] - sc * m;
    float4* p = (float4*)(data + (size_t)ch * per_chan);
    int i = blockIdx.x * blockDim.x + threadIdx.x;
    float4 t = p[i];
    t.x = fmaxf(fmaf(t.x, sc, sh), 0.f);
    t.y = fmaxf(fmaf(t.y, sc, sh), 0.f);
    t.z = fmaxf(fmaf(t.z, sc, sh), 0.f);
    t.w = fmaxf(fmaf(t.w, sc, sh), 0.f);
    p[i] = t;
}

// ---------------- FC with fused BN3 + tanh -----------------------------------
__global__ void fc_partial_kernel(const float* __restrict__ h, const float* __restrict__ Wfc,
                                  const float* __restrict__ stats, const float* __restrict__ g,
                                  const float* __restrict__ be, float inv_n) {
    const int FCH = 256;
    int b  = blockIdx.x * 128 + threadIdx.x;
    int f0 = blockIdx.y * FCH;
    __shared__ float Wsm[10 * FCH];
    __shared__ float fsc[FCH], fsh[FCH];
    for (int i = threadIdx.x; i < 10 * FCH; i += 128) {
        int t = i / FCH, f = i % FCH;
        Wsm[i] = Wfc[t * 6400 + f0 + f];
    }
    for (int f = threadIdx.x; f < FCH; f += 128) {
        int ch = (f0 + f) / 100;
        float m  = stats[ch * 2 + 0] * inv_n;
        float v  = stats[ch * 2 + 1] * inv_n - m * m;
        float sc = g[ch] * rsqrtf(v + EPSV);
        fsc[f] = sc;
        fsh[f] = be[ch] - sc * m;
    }
    __syncthreads();
    float acc[10];
#pragma unroll
    for (int t = 0; t < 10; t++) acc[t] = 0.f;
    for (int f = 0; f < FCH; f++) {
        float v = h[(size_t)(f0 + f) * 1024 + b];
        v = tanhf(fmaf(v, fsc[f], fsh[f]));
#pragma unroll
        for (int t = 0; t < 10; t++) acc[t] = fmaf(v, Wsm[t * FCH + f], acc[t]);
    }
#pragma unroll
    for (int t = 0; t < 10; t++)
        g_part[((size_t)blockIdx.y * 10 + t) * 1024 + b] = acc[t];
}

__global__ void fc_reduce_kernel(const float* __restrict__ fcb, float* __restrict__ out) {
    int idx = blockIdx.x * blockDim.x + threadIdx.x;
    if (idx >= 10240) return;
    int b = idx / 10, t = idx % 10;
    float s = fcb[t];
#pragma unroll
    for (int c = 0; c < 25; c++) s += g_part[((size_t)c * 10 + t) * 1024 + b];
    out[b * 10 + t] = s;
}

// ---------------- launch -----------------------------------------------------
extern "C" void kernel_launch(void* const* d_in, const int* in_sizes, int n_in,
                              void* d_out, int out_size) {
    const float* x   = (const float*)d_in[0];
    const float* W1  = (const float*)d_in[1];
    const float* b1  = (const float*)d_in[2];
    const float* g1  = (const float*)d_in[3];
    const float* be1 = (const float*)d_in[4];
    const float* W2  = (const float*)d_in[5];
    const float* b2  = (const float*)d_in[6];
    const float* g2  = (const float*)d_in[7];
    const float* be2 = (const float*)d_in[8];
    const float* W3  = (const float*)d_in[9];
    const float* b3  = (const float*)d_in[10];
    const float* g3  = (const float*)d_in[11];
    const float* be3 = (const float*)d_in[12];
    const float* fcW = (const float*)d_in[13];
    const float* fcb = (const float*)d_in[14];
    float* out = (float*)d_out;

    float *p_xt, *p_h1, *p_h2, *p_h3, *p_stats, *p_w1t, *p_w2t, *p_w3t;
    cudaGetSymbolAddress((void**)&p_xt, g_xt);
    cudaGetSymbolAddress((void**)&p_h1, g_h1);
    cudaGetSymbolAddress((void**)&p_h2, g_h2);
    cudaGetSymbolAddress((void**)&p_h3, g_h3);
    cudaGetSymbolAddress((void**)&p_stats, g_stats);
    cudaGetSymbolAddress((void**)&p_w1t, g_w1t);
    cudaGetSymbolAddress((void**)&p_w2t, g_w2t);
    cudaGetSymbolAddress((void**)&p_w3t, g_w3t);

    // smem: 16 outputs * (C/KH)*10 padded k-slots * 8B
    const int sm1 = 16 * 1 * 10 * 8;      // 1.28 KB (KH=1)
    const int sm2 = 16 * 16 * 10 * 8;     // 20.5 KB (KH=1)
    const int sm3 = 16 * 16 * 10 * 8;     // 20.5 KB (KH=2: 16 of 32 channels staged)
    cudaFuncSetAttribute((const void*)lc_kernel<1, 16, 14, 16, 1, 8>,
                         cudaFuncAttributeMaxDynamicSharedMemorySize, sm1);
    cudaFuncSetAttribute((const void*)lc_kernel<16, 14, 12, 32, 1, 8>,
                         cudaFuncAttributeMaxDynamicSharedMemorySize, sm2);
    cudaFuncSetAttribute((const void*)lc_kernel<32, 12, 10, 64, 2, 8>,
                         cudaFuncAttributeMaxDynamicSharedMemorySize, sm3);

    int wblocks = 257 + (28224 + 663552 + 1843200 + 255) / 256;
    prep_kernel<<<wblocks, 256>>>(x, W1, W2, W3);

    // #1 LC1, #2 bn1, #3 LC2 (profiled slot — control, expect ~54us)
    lc_kernel<1, 16, 14, 16, 1, 8><<<dim3(196, 4, 1), dim3(32, 2), sm1>>>(
        p_xt, p_w1t, b1, p_h1, p_stats + 0);
    bn_relu_kernel<<<dim3(196, 16), 256>>>(p_stats + 0, g1, be1, p_h1,
                                           14 * 14 * 1024, 1.f / (14.f * 14.f * 1024.f));
    lc_kernel<16, 14, 12, 32, 1, 8><<<dim3(144, 4, 2), dim3(32, 2), sm2>>>(
        p_h1, p_w2t, b2, p_h2, p_stats + 32);
    bn_relu_kernel<<<dim3(144, 32), 256>>>(p_stats + 32, g2, be2, p_h2,
                                           12 * 12 * 1024, 1.f / (12.f * 12.f * 1024.f));
    // LC3: KH=2 halves smem -> 8 blocks/SM (reg-bound) instead of 5 (smem-bound)
    lc_kernel<32, 12, 10, 64, 2, 8><<<dim3(100, 4, 4), dim3(32, 2), sm3>>>(
        p_h2, p_w3t, b3, p_h3, p_stats + 96);

    fc_partial_kernel<<<dim3(8, 25), 128>>>(p_h3, fcW, p_stats + 96, g3, be3,
                                            1.f / (10.f * 10.f * 1024.f));
    fc_reduce_kernel<<<40, 256>>>(fcb, out);
}